// round 13
// baseline (speedup 1.0000x reference)
#include <cuda_runtime.h>

#define N 384
#define D 512
#define MARGIN 0.5f
#define EPS 1e-6f
#define BLK 384
#define NWARP (BLK / 32)
#define GRID (N / 2)          // 192 blocks, 2 anchors each

// Finalize scratch; zero-initialized at load, winner resets each launch so
// graph replays start clean.
__device__ float g_acc;
__device__ int   g_cnt;

__device__ __forceinline__ float warp_sum(float v) {
#pragma unroll
    for (int o = 16; o; o >>= 1) v += __shfl_xor_sync(0xffffffffu, v, o);
    return v;
}

__global__ __launch_bounds__(BLK) void triplet_fused_kernel(
    const float* __restrict__ features,
    const int*   __restrict__ labels,
    const int*   __restrict__ levels,
    float*       __restrict__ out) {
    __shared__ int   s_list0[N], s_list1[N];    // [0..npos) pos, [npos..) neg
    __shared__ float s_dc0[N],   s_dc1[N];      // dist per compacted ordinal
    __shared__ int   s_wp0[NWARP], s_wn0[NWARP];
    __shared__ int   s_wp1[NWARP], s_wn1[NWARP];

    const int i0   = blockIdx.x;            // anchor A
    const int i1   = blockIdx.x + GRID;     // anchor B
    const int t    = threadIdx.x;
    const int wid  = t >> 5;
    const int lane = t & 31;

    const int lab0 = labels[i0];            // broadcasts
    const int lev0 = levels[i0];
    const int lab1 = labels[i1];
    const int lev1 = levels[i1];
    const int lab_t = labels[t];            // coalesced (single pass, both anchors)
    const int lev_t = levels[t];

    const bool same0 = (t != i0) && (lab_t == lab0);
    const bool pos0  = same0 && (lev_t == lev0);
    const bool neg0  = same0 && !pos0;
    const bool same1 = (t != i1) && (lab_t == lab1);
    const bool pos1  = same1 && (lev_t == lev1);
    const bool neg1  = same1 && !pos1;

    const unsigned bp0 = __ballot_sync(0xffffffffu, pos0);
    const unsigned bn0 = __ballot_sync(0xffffffffu, neg0);
    const unsigned bp1 = __ballot_sync(0xffffffffu, pos1);
    const unsigned bn1 = __ballot_sync(0xffffffffu, neg1);
    if (lane == 0) {
        s_wp0[wid] = __popc(bp0); s_wn0[wid] = __popc(bn0);
        s_wp1[wid] = __popc(bp1); s_wn1[wid] = __popc(bn1);
    }
    __syncthreads();

    // Register prefix over 12 warp counts (both anchors, paid once).
    int bP0 = 0, bN0 = 0, nP0 = 0, nN0 = 0;
    int bP1 = 0, bN1 = 0, nP1 = 0, nN1 = 0;
#pragma unroll
    for (int w = 0; w < NWARP; w++) {
        const int p0 = s_wp0[w], n0 = s_wn0[w], p1 = s_wp1[w], n1 = s_wn1[w];
        if (w < wid) { bP0 += p0; bN0 += n0; bP1 += p1; bN1 += n1; }
        nP0 += p0; nN0 += n0; nP1 += p1; nN1 += n1;
    }
    const unsigned lt = (1u << lane) - 1u;
    if (pos0) s_list0[bP0 + __popc(bp0 & lt)] = t;
    if (neg0) s_list0[nP0 + bN0 + __popc(bn0 & lt)] = t;
    if (pos1) s_list1[bP1 + __popc(bp1 & lt)] = t;
    if (neg1) s_list1[nP1 + bN1 + __popc(bn1 & lt)] = t;
    __syncthreads();

    // ---- distances: warps round-robin over BOTH anchors' combined list ----
    const int ns0   = nP0 + nN0;
    const int total = ns0 + nP1 + nN1;
    for (int m = wid; m < total; m += NWARP) {
        const bool selB = (m >= ns0);
        const int  mm   = selB ? (m - ns0) : m;
        const int  j    = selB ? s_list1[mm] : s_list0[mm];
        const int  ia   = selB ? i1 : i0;

        const float4* __restrict__ fa = (const float4*)(features + ia * D);
        const float4* __restrict__ fj = (const float4*)(features + j * D);
        float acc = 0.0f;
#pragma unroll
        for (int u = 0; u < 4; u++) {
            const int idx = u * 32 + lane;   // coalesced per warp, MLP=4
            float4 a = fa[idx];              // anchor row: L1-hit after 1st pair
            float4 b = fj[idx];
            float d0 = a.x - b.x + EPS;      // torch pairwise_distance eps
            float d1 = a.y - b.y + EPS;
            float d2 = a.z - b.z + EPS;
            float d3 = a.w - b.w + EPS;
            acc = fmaf(d0, d0, acc);
            acc = fmaf(d1, d1, acc);
            acc = fmaf(d2, d2, acc);
            acc = fmaf(d3, d3, acc);
        }
        acc = warp_sum(acc);
        if (lane == 0) {
            if (selB) s_dc1[mm] = sqrtf(acc);
            else      s_dc0[mm] = sqrtf(acc);
        }
    }
    __syncthreads();

    // ---- warp 0: hinge for both anchors (lane-strided) + single finalize ----
    if (wid == 0) {
        float contrib = 0.0f;

        const int npair0 = nP0 * nN0;
        float a0 = 0.0f;
        for (int p = lane; p < npair0; p += 32) {
            const int a = p / nN0;
            const int q = p - a * nN0;
            a0 += fmaxf(s_dc0[a] - s_dc0[nP0 + q] + MARGIN, 0.0f);
        }
        a0 = warp_sum(a0);
        if (npair0 > 0) contrib += a0 / (float)npair0;

        const int npair1 = nP1 * nN1;
        float a1 = 0.0f;
        for (int p = lane; p < npair1; p += 32) {
            const int a = p / nN1;
            const int q = p - a * nN1;
            a1 += fmaxf(s_dc1[a] - s_dc1[nP1 + q] + MARGIN, 0.0f);
        }
        a1 = warp_sum(a1);
        if (npair1 > 0) contrib += a1 / (float)npair1;

        if (lane == 0) {
            atomicAdd(&g_acc, contrib * (1.0f / (float)N));  // REDG
            __threadfence();
            if (atomicAdd(&g_cnt, 1) == GRID - 1) {
                g_cnt = 0;
                out[0] = atomicExch(&g_acc, 0.0f);  // read + reset for replay
            }
        }
    }
}

extern "C" void kernel_launch(void* const* d_in, const int* in_sizes, int n_in,
                              void* d_out, int out_size) {
    const float* features = (const float*)d_in[0];
    const int*   labels   = (const int*)d_in[1];
    const int*   levels   = (const int*)d_in[2];
    float* out = (float*)d_out;

    triplet_fused_kernel<<<GRID, BLK>>>(features, labels, levels, out);
}

// round 14
// speedup vs baseline: 1.2694x; 1.2694x over previous
#include <cuda_runtime.h>

#define N 384
#define D 512
#define MARGIN 0.5f
#define EPS 1e-6f
#define BLK 384
#define NWARP (BLK / 32)

// Per-anchor partial contributions. Written by plain STG in kernel 1, read by
// kernel 2 (kernel boundary orders the memory). No atomics anywhere.
__device__ float g_part[N];

__device__ __forceinline__ float warp_sum(float v) {
#pragma unroll
    for (int o = 16; o; o >>= 1) v += __shfl_xor_sync(0xffffffffu, v, o);
    return v;
}

__global__ __launch_bounds__(BLK) void triplet_main_kernel(
    const float* __restrict__ features,
    const int*   __restrict__ labels,
    const int*   __restrict__ levels) {
    __shared__ int   s_list[N];      // [0..npos) positives, [npos..npos+nneg) negatives
    __shared__ float s_distc[N];     // distance per compacted ordinal
    __shared__ int   s_wpos[NWARP];
    __shared__ int   s_wneg[NWARP];

    const int i    = blockIdx.x;
    const int t    = threadIdx.x;
    const int wid  = t >> 5;
    const int lane = t & 31;

    // Anchor row -> registers FIRST: overlaps the fetch with label loads,
    // ballots and both compaction barriers. L1-broadcast across warps.
    const float4* __restrict__ fi = (const float4*)(features + i * D);
    const float4 a0 = fi[lane];
    const float4 a1 = fi[32 + lane];
    const float4 a2 = fi[64 + lane];
    const float4 a3 = fi[96 + lane];

    const int lab_i = labels[i];     // broadcast: one L2 transaction
    const int lev_i = levels[i];
    const int lab_t = labels[t];     // coalesced
    const int lev_t = levels[t];

    const bool same   = (t != i) && (lab_t == lab_i);
    const bool is_pos = same && (lev_t == lev_i);
    const bool is_neg = same && !is_pos;

    const unsigned bal_pos = __ballot_sync(0xffffffffu, is_pos);
    const unsigned bal_neg = __ballot_sync(0xffffffffu, is_neg);
    if (lane == 0) {
        s_wpos[wid] = __popc(bal_pos);
        s_wneg[wid] = __popc(bal_neg);
    }
    __syncthreads();

    // Register prefix over 12 warp counts (paid once).
    int base_p = 0, base_n = 0, npos = 0, nneg = 0;
#pragma unroll
    for (int w = 0; w < NWARP; w++) {
        const int cp = s_wpos[w], cn = s_wneg[w];
        if (w < wid) { base_p += cp; base_n += cn; }
        npos += cp;
        nneg += cn;
    }
    if (is_pos) s_list[base_p + __popc(bal_pos & ((1u << lane) - 1u))] = t;
    if (is_neg) s_list[npos + base_n + __popc(bal_neg & ((1u << lane) - 1u))] = t;
    __syncthreads();

    // ---- distances: warps round-robin over the compacted list (balanced) ----
    const int nsame = npos + nneg;
    for (int m = wid; m < nsame; m += NWARP) {
        const int j = s_list[m];
        const float4* __restrict__ fj = (const float4*)(features + j * D);
        const float4 b0 = fj[lane];
        const float4 b1 = fj[32 + lane];
        const float4 b2 = fj[64 + lane];
        const float4 b3 = fj[96 + lane];

        float acc = 0.0f, d;
        d = a0.x - b0.x + EPS; acc = fmaf(d, d, acc);   // torch eps convention
        d = a0.y - b0.y + EPS; acc = fmaf(d, d, acc);
        d = a0.z - b0.z + EPS; acc = fmaf(d, d, acc);
        d = a0.w - b0.w + EPS; acc = fmaf(d, d, acc);
        d = a1.x - b1.x + EPS; acc = fmaf(d, d, acc);
        d = a1.y - b1.y + EPS; acc = fmaf(d, d, acc);
        d = a1.z - b1.z + EPS; acc = fmaf(d, d, acc);
        d = a1.w - b1.w + EPS; acc = fmaf(d, d, acc);
        d = a2.x - b2.x + EPS; acc = fmaf(d, d, acc);
        d = a2.y - b2.y + EPS; acc = fmaf(d, d, acc);
        d = a2.z - b2.z + EPS; acc = fmaf(d, d, acc);
        d = a2.w - b2.w + EPS; acc = fmaf(d, d, acc);
        d = a3.x - b3.x + EPS; acc = fmaf(d, d, acc);
        d = a3.y - b3.y + EPS; acc = fmaf(d, d, acc);
        d = a3.z - b3.z + EPS; acc = fmaf(d, d, acc);
        d = a3.w - b3.w + EPS; acc = fmaf(d, d, acc);
        acc = warp_sum(acc);
        if (lane == 0) s_distc[m] = sqrtf(acc);
    }
    __syncthreads();

    // ---- warp 0: full hinge (npos*nneg terms) + plain store of partial ----
    if (wid == 0) {
        float acc = 0.0f;
        const int npair = npos * nneg;
        for (int p = lane; p < npair; p += 32) {
            const int a = p / nneg;          // positive ordinal
            const int q = p - a * nneg;      // negative ordinal
            acc += fmaxf(s_distc[a] - s_distc[npos + q] + MARGIN, 0.0f);
        }
        acc = warp_sum(acc);
        if (lane == 0) {
            float contrib = 0.0f;
            if (npair > 0) contrib = acc / (float)npair * (1.0f / (float)N);
            g_part[i] = contrib;             // plain STG — no fence, no atomic
        }
    }
}

// One block: reduce the 384 partials and write the scalar output.
__global__ __launch_bounds__(BLK) void triplet_reduce_kernel(float* __restrict__ out) {
    __shared__ float s_w[NWARP];
    const int t    = threadIdx.x;
    const int wid  = t >> 5;
    const int lane = t & 31;

    float v = warp_sum(g_part[t]);
    if (lane == 0) s_w[wid] = v;
    __syncthreads();

    if (wid == 0) {
        float x = (lane < NWARP) ? s_w[lane] : 0.0f;
#pragma unroll
        for (int o = 8; o; o >>= 1) x += __shfl_xor_sync(0xffffffffu, x, o);
        if (lane == 0) out[0] = x;
    }
}

extern "C" void kernel_launch(void* const* d_in, const int* in_sizes, int n_in,
                              void* d_out, int out_size) {
    const float* features = (const float*)d_in[0];
    const int*   labels   = (const int*)d_in[1];
    const int*   levels   = (const int*)d_in[2];
    float* out = (float*)d_out;

    triplet_main_kernel<<<N, BLK>>>(features, labels, levels);
    triplet_reduce_kernel<<<1, BLK>>>(out);
}